// round 4
// baseline (speedup 1.0000x reference)
#include <cuda_runtime.h>
#include <math_constants.h>

// Scratch + sync state (no dynamic allocation allowed).
__device__ float g_P4[2 * 256];          // maxpool16(x4)  [b, hw]
__device__ float g_T3[2 * 256 * 256];    // maxpool8(x3)   [b, j, hw]
__device__ int   g_done   = 0;           // prologue blocks completed
__device__ int   g_finish = 0;           // all blocks completed (for reset)

#define N_PRO   1024                      // prologue blocks
#define N_MAIN  8192                      // main blocks
#define N_TOTAL (N_PRO + N_MAIN)

// ---------------------------------------------------------------------------
// Single fused kernel, grid = 9216 x 256.
//   bid [0, 512):     T3[b, j, hw] = maxpool8(x3[b,j])     (x3: [2,256,128,128])
//   bid [512, 1024):  P4[b, hw]    = maxpool16(x4[b,0])    (x4: [2,1,256,256])
//     ... both signal g_done (release).
//   bid [1024, 9216): main block (b, k): read+pool x2/x1 into registers,
//     spin-wait g_done==1024 (acquire), then combine with T3/P4 and stream
//     ff/out. Prologue bids come first -> dispatched first -> no deadlock.
// The last block to finish resets the counters so graph replays start clean.
// ---------------------------------------------------------------------------
__global__ void __launch_bounds__(256) fused_all_kernel(
        const float* __restrict__ x1, const float* __restrict__ x2,
        const float* __restrict__ x3, const float* __restrict__ x4,
        const float* __restrict__ ff, float* __restrict__ out) {
    const int bid = blockIdx.x;
    const int t   = threadIdx.x;

    if (bid < N_PRO) {
        if (bid < 512) {
            // ---- maxpool8 of one x3 plane ----
            const int b  = bid >> 8, j = bid & 255;
            const int oh = t >> 4, ow = t & 15;
            const float* base = x3 + ((size_t)b * 256 + j) * 16384;
            float m = -CUDART_INF_F;
#pragma unroll
            for (int r = 0; r < 8; ++r) {
                float4 v0 = __ldcs((const float4*)(base + (8 * oh + r) * 128 + 8 * ow));
                float4 v1 = __ldcs((const float4*)(base + (8 * oh + r) * 128 + 8 * ow) + 1);
                m = fmaxf(m, fmaxf(fmaxf(v0.x, v0.y), fmaxf(v0.z, v0.w)));
                m = fmaxf(m, fmaxf(fmaxf(v1.x, v1.y), fmaxf(v1.z, v1.w)));
            }
            g_T3[((size_t)b * 256 + j) * 256 + t] = m;
        } else {
            // ---- maxpool16 of x4: one output value per block, tree reduce ----
            const int o  = bid - 512;          // [0, 512)
            const int b  = o >> 8;
            const int p  = o & 255;
            const int oh = p >> 4, ow = p & 15;
            const float* base = x4 + (size_t)b * 65536;
            float v = base[(16 * oh + (t >> 4)) * 256 + 16 * ow + (t & 15)];

            __shared__ float red[8];
#pragma unroll
            for (int s = 16; s > 0; s >>= 1)
                v = fmaxf(v, __shfl_down_sync(0xFFFFFFFFu, v, s));
            if ((t & 31) == 0) red[t >> 5] = v;
            __syncthreads();
            if (t == 0) {
                float m = red[0];
#pragma unroll
                for (int w = 1; w < 8; ++w) m = fmaxf(m, red[w]);
                g_P4[b * 256 + p] = m;
            }
        }
        // Signal: this prologue block's T3/P4 writes are visible.
        __syncthreads();
        if (t == 0) {
            __threadfence();                   // release
            atomicAdd(&g_done, 1);
        }
    } else {
        // ================= main block =================
        const int B  = bid - N_PRO;            // [0, 8192)
        const int b  = B >> 12, k = B & 4095;
        const int oh = t >> 4, ow = t & 15;

        // ---- prologue-independent HBM reads (overlap with prologue) ----
        const float* x2p = x2 + ((size_t)b * 4096 + k) * 4096;
        float p2 = -CUDART_INF_F;
#pragma unroll
        for (int r = 0; r < 4; ++r) {
            float4 v = __ldcs((const float4*)(x2p + (4 * oh + r) * 64 + 4 * ow));
            p2 = fmaxf(p2, fmaxf(fmaxf(v.x, v.y), fmaxf(v.z, v.w)));
        }

        float p1v[4];
#pragma unroll
        for (int m = 0; m < 4; ++m) {
            const int c = k + 4096 * m;
            const float* x1p = x1 + ((size_t)b * 16384 + c) * 1024;
            float2 a0 = __ldcs((const float2*)(x1p + (2 * oh)     * 32 + 2 * ow));
            float2 a1 = __ldcs((const float2*)(x1p + (2 * oh + 1) * 32 + 2 * ow));
            p1v[m] = fmaxf(fmaxf(a0.x, a0.y), fmaxf(a1.x, a1.y));
        }

        // ---- wait for prologue (acquire) ----
        if (*(volatile int*)&g_done < N_PRO) {
            while (*(volatile int*)&g_done < N_PRO) __nanosleep(128);
        }
        __threadfence();                       // acquire side of the handshake
        __syncthreads();                       // keep block convergent past wait

        const float basev = p2
                          + g_T3[((size_t)b * 256 + (k & 255)) * 256 + t]
                          + g_P4[b * 256 + t];

#pragma unroll
        for (int m = 0; m < 4; ++m) {
            const int c = k + 4096 * m;
            const float s = basev + p1v[m];
            const size_t o0 = ((size_t)b * 32768 + c) * 256 + t;
            const size_t o1 = o0 + (size_t)16384 * 256;
            __stcs(out + o0, fmaxf(s + __ldcs(ff + o0), 0.0f));
            __stcs(out + o1, fmaxf(s + __ldcs(ff + o1), 0.0f));
        }
    }

    // ---- replay-safe counter reset: last block of the grid cleans up ----
    __syncthreads();
    if (t == 0) {
        const int old = atomicAdd(&g_finish, 1);
        if (old == N_TOTAL - 1) {
            g_done   = 0;
            g_finish = 0;
            __threadfence();
        }
    }
}

// ---------------------------------------------------------------------------
// Launch: inputs in metadata order: x1, x2, x3, x4, pure_ff
// ---------------------------------------------------------------------------
extern "C" void kernel_launch(void* const* d_in, const int* in_sizes, int n_in,
                              void* d_out, int out_size) {
    const float* x1 = (const float*)d_in[0];
    const float* x2 = (const float*)d_in[1];
    const float* x3 = (const float*)d_in[2];
    const float* x4 = (const float*)d_in[3];
    const float* ff = (const float*)d_in[4];
    float* out = (float*)d_out;

    fused_all_kernel<<<N_TOTAL, 256>>>(x1, x2, x3, x4, ff, out);
}

// round 5
// speedup vs baseline: 1.4024x; 1.4024x over previous
#include <cuda_runtime.h>
#include <math_constants.h>

// Scratch (no dynamic allocation allowed).
__device__ float g_P4[2 * 256];          // maxpool16(x4)  [b, hw]
__device__ float g_T3[2 * 256 * 256];    // maxpool8(x3)   [b, j, hw]

// ---------------------------------------------------------------------------
// Prologue kernel, grid = 2560 x 256. PDL-triggers at entry so the main kernel
// can launch concurrently.
//   bid [0, 2048):    quarter-plane maxpool8 of x3 (x3: [2,256,128,128])
//                     block = (b, j, quarter); 32 input rows -> 4 T3 rows.
//                     4 threads per 8x8 window, shuffle-reduced.
//   bid [2048, 2560): P4[b, hw] = maxpool16(x4[b,0])  (x4: [2,1,256,256])
//                     one block per output value, tree reduction.
// ---------------------------------------------------------------------------
__global__ void __launch_bounds__(256) prologue_kernel(
        const float* __restrict__ x3, const float* __restrict__ x4) {
#if __CUDA_ARCH__ >= 900
    cudaTriggerProgrammaticLaunchCompletion();
#endif
    const int bid = blockIdx.x;
    const int t   = threadIdx.x;

    if (bid < 2048) {
        // ---- quarter-plane maxpool8 of x3 ----
        const int b  = bid >> 10;            // [0,2)
        const int r  = bid & 1023;
        const int j  = r >> 2;               // channel [0,256)
        const int q  = r & 3;                // quarter [0,4)

        // 64 outputs per block (4 rows x 16 cols); 4 threads per output.
        const int out_idx = t >> 2;          // [0,64)
        const int sub     = t & 3;           // [0,4)
        const int oh_l    = out_idx >> 4;    // [0,4)  local output row
        const int ow      = out_idx & 15;    // [0,16) output col

        const float* base = x3 + ((size_t)b * 256 + j) * 16384;
        const int row0 = 8 * (q * 4 + oh_l) + sub * 2;   // this thread's 2 rows
        const float* r0 = base + row0 * 128 + 8 * ow;
        const float* r1 = r0 + 128;

        float4 a0 = *(const float4*)(r0);
        float4 a1 = *(const float4*)(r0 + 4);
        float4 b0 = *(const float4*)(r1);
        float4 b1 = *(const float4*)(r1 + 4);
        float m = fmaxf(fmaxf(fmaxf(a0.x, a0.y), fmaxf(a0.z, a0.w)),
                        fmaxf(fmaxf(a1.x, a1.y), fmaxf(a1.z, a1.w)));
        m = fmaxf(m, fmaxf(fmaxf(fmaxf(b0.x, b0.y), fmaxf(b0.z, b0.w)),
                           fmaxf(fmaxf(b1.x, b1.y), fmaxf(b1.z, b1.w))));

        // reduce across the 4 sub-threads (consecutive lanes)
        m = fmaxf(m, __shfl_down_sync(0xFFFFFFFFu, m, 2));
        m = fmaxf(m, __shfl_down_sync(0xFFFFFFFFu, m, 1));
        if (sub == 0) {
            const int hw = (q * 4 + oh_l) * 16 + ow;
            g_T3[((size_t)b * 256 + j) * 256 + hw] = m;
        }
    } else {
        // ---- maxpool16 of x4: one output value per block, tree reduction ----
        const int o  = bid - 2048;           // [0, 512)
        const int b  = o >> 8;
        const int p  = o & 255;
        const int oh = p >> 4, ow = p & 15;
        const float* base = x4 + (size_t)b * 65536;
        float v = base[(16 * oh + (t >> 4)) * 256 + 16 * ow + (t & 15)];

        __shared__ float red[8];
#pragma unroll
        for (int s = 16; s > 0; s >>= 1)
            v = fmaxf(v, __shfl_down_sync(0xFFFFFFFFu, v, s));
        if ((t & 31) == 0) red[t >> 5] = v;
        __syncthreads();
        if (t == 0) {
            float m = red[0];
#pragma unroll
            for (int w = 1; w < 8; ++w) m = fmaxf(m, red[w]);
            g_P4[b * 256 + p] = m;
        }
    }
}

// ---------------------------------------------------------------------------
// Fused main kernel: one block per (b, k), k in [0,4096).
// PDL-launched: starts while the prologue runs; all x2/x1 reads happen before
// cudaGridDependencySynchronize(), only T3/P4 adds + ff/out streaming after.
//   base = maxpool4(x2[b,k]) + T3[b, k%256, t] + P4[b, t]
//   for m in 0..3:  c = k + 4096*m
//     out[b,c]       = relu(base + maxpool2(x1[b,c]) + ff[b,c])
//     out[b,c+16384] = relu(  "                      + ff[b,c+16384])
// ---------------------------------------------------------------------------
__global__ void __launch_bounds__(256) fused_main_kernel(
        const float* __restrict__ x1, const float* __restrict__ x2,
        const float* __restrict__ ff, float* __restrict__ out) {
    const int B  = blockIdx.x;           // [0, 8192)
    const int b  = B >> 12, k = B & 4095;
    const int t  = threadIdx.x;          // [0, 256)
    const int oh = t >> 4, ow = t & 15;

    // ---- prologue-independent reads: x2 pool4 ----
    const float* x2p = x2 + ((size_t)b * 4096 + k) * 4096;
    float p2 = -CUDART_INF_F;
#pragma unroll
    for (int r = 0; r < 4; ++r) {
        float4 v = *(const float4*)(x2p + (4 * oh + r) * 64 + 4 * ow);
        p2 = fmaxf(p2, fmaxf(fmaxf(v.x, v.y), fmaxf(v.z, v.w)));
    }

    // ---- prologue-independent reads: x1 pool2 for all 4 aliases ----
    float p1v[4];
#pragma unroll
    for (int m = 0; m < 4; ++m) {
        const int c = k + 4096 * m;
        const float* x1p = x1 + ((size_t)b * 16384 + c) * 1024;
        float2 a0 = *(const float2*)(x1p + (2 * oh)     * 32 + 2 * ow);
        float2 a1 = *(const float2*)(x1p + (2 * oh + 1) * 32 + 2 * ow);
        p1v[m] = fmaxf(fmaxf(a0.x, a0.y), fmaxf(a1.x, a1.y));
    }

    // ---- wait for prologue grid (T3, P4 visible) ----
#if __CUDA_ARCH__ >= 900
    cudaGridDependencySynchronize();
#endif

    const float basev = p2
                      + g_T3[((size_t)b * 256 + (k & 255)) * 256 + t]
                      + g_P4[b * 256 + t];

#pragma unroll
    for (int m = 0; m < 4; ++m) {
        const int c = k + 4096 * m;
        const float s = basev + p1v[m];
        const size_t o0 = ((size_t)b * 32768 + c) * 256 + t;
        const size_t o1 = o0 + (size_t)16384 * 256;
        out[o0] = fmaxf(s + ff[o0], 0.0f);
        out[o1] = fmaxf(s + ff[o1], 0.0f);
    }
}

// ---------------------------------------------------------------------------
// Launch: inputs in metadata order: x1, x2, x3, x4, pure_ff
// ---------------------------------------------------------------------------
extern "C" void kernel_launch(void* const* d_in, const int* in_sizes, int n_in,
                              void* d_out, int out_size) {
    const float* x1 = (const float*)d_in[0];
    const float* x2 = (const float*)d_in[1];
    const float* x3 = (const float*)d_in[2];
    const float* x4 = (const float*)d_in[3];
    const float* ff = (const float*)d_in[4];
    float* out = (float*)d_out;

    prologue_kernel<<<2560, 256>>>(x3, x4);

    cudaLaunchConfig_t cfg = {};
    cfg.gridDim  = dim3(8192, 1, 1);
    cfg.blockDim = dim3(256, 1, 1);
    cfg.dynamicSmemBytes = 0;
    cfg.stream = 0;
    cudaLaunchAttribute attrs[1];
    attrs[0].id = cudaLaunchAttributeProgrammaticStreamSerialization;
    attrs[0].val.programmaticStreamSerializationAllowed = 1;
    cfg.attrs = attrs;
    cfg.numAttrs = 1;
    cudaLaunchKernelEx(&cfg, fused_main_kernel, x1, x2, ff, out);
}